// round 12
// baseline (speedup 1.0000x reference)
#include <cuda_runtime.h>
#include <cstdint>

// MultiIndexSelect: out[to_k[i]] = mat_k[from_k[i]], k=0..2, L=400000, D=64 f32.
// R4/R10/R11 all pin DRAM at 61-66% regardless of MLP/occ -> ceiling is DRAM
// random-access efficiency. to0|to1|to2 is a full permutation of [0,3L), so:
//   Pass 1: inv[to_k[i]] = k*L + i   (1.2M 4B scatters into 4.8MB array -> L2)
//   Pass 2: iterate OUTPUT rows in order: gather stays random (compulsory), but
//           stores become perfectly sequential streaming -> ~95% write efficiency.

static constexpr int MAX_OUT_ROWS = 1200000;           // 3*L for this problem
__device__ int g_inv[MAX_OUT_ROWS];

__global__ __launch_bounds__(256) void build_inverse_kernel(
    const int* __restrict__ t0,
    const int* __restrict__ t1,
    const int* __restrict__ t2,
    int L)
{
    int i = blockIdx.x * blockDim.x + threadIdx.x;
    int total = 3 * L;
    if (i >= total) return;
    int dst, code = i;                                 // code = k*L + i, k-major
    if (i < L)            dst = __ldg(&t0[i]);
    else if (i < 2 * L)   dst = __ldg(&t1[i - L]);
    else                  dst = __ldg(&t2[i - 2 * L]);
    g_inv[dst] = code;
}

static constexpr int UNROLL = 4;

__global__ __launch_bounds__(256) void gather_seqwrite_kernel(
    const float4* __restrict__ m0,
    const float4* __restrict__ m1,
    const float4* __restrict__ m2,
    const int* __restrict__ f0,
    const int* __restrict__ f1,
    const int* __restrict__ f2,
    float4* __restrict__ out,
    int L)
{
    const unsigned total = 3u * (unsigned)L * 16u;     // 19.2M float4 slots
    const unsigned base  = blockIdx.x * (blockDim.x * UNROLL) + threadIdx.x;

    float4   val[UNROLL];
    unsigned oslot[UNROLL];
    bool     ok[UNROLL];

    // Batched: inv read (broadcast across 16-lane group), from read (L2-hot),
    // random 256B gather. All loads front-batched for MLP=4 (R4-proven regime).
    #pragma unroll
    for (int u = 0; u < UNROLL; u++) {
        unsigned tid = base + u * blockDim.x;
        ok[u] = (tid < total);
        if (ok[u]) {
            unsigned orow = tid >> 4;                  // sequential output row
            unsigned lane = tid & 15u;
            int code = __ldg(&g_inv[orow]);            // k*L + i
            const float4* __restrict__ mat;
            int src;
            if (code < L) {
                mat = m0; src = __ldg(&f0[code]);
            } else if (code < 2 * L) {
                mat = m1; src = __ldg(&f1[code - L]);
            } else {
                mat = m2; src = __ldg(&f2[code - 2 * L]);
            }
            oslot[u] = orow * 16u + lane;              // coalesced destination
            val[u]   = __ldcs(&mat[(size_t)src * 16u + lane]);
        }
    }

    // Sequential streaming stores: warp writes 512B contiguous per slot-step.
    #pragma unroll
    for (int u = 0; u < UNROLL; u++) {
        if (ok[u]) __stcs(&out[oslot[u]], val[u]);
    }
}

extern "C" void kernel_launch(void* const* d_in, const int* in_sizes, int n_in,
                              void* d_out, int out_size)
{
    const float4* m0 = (const float4*)d_in[0];
    const float4* m1 = (const float4*)d_in[1];
    const float4* m2 = (const float4*)d_in[2];
    const int* f0 = (const int*)d_in[3];
    const int* f1 = (const int*)d_in[4];
    const int* f2 = (const int*)d_in[5];
    const int* t0 = (const int*)d_in[6];
    const int* t1 = (const int*)d_in[7];
    const int* t2 = (const int*)d_in[8];

    int L = in_sizes[3];                                // 400000

    // Pass 1: build inverse permutation (scatter lands in L2; ~5us).
    {
        int total = 3 * L;
        int threads = 256;
        int blocks = (total + threads - 1) / threads;
        build_inverse_kernel<<<blocks, threads>>>(t0, t1, t2, L);
    }

    // Pass 2: random gather + sequential streaming write.
    {
        unsigned total = 3u * (unsigned)L * 16u;
        int threads = 256;
        unsigned per_block = threads * UNROLL;
        unsigned blocks = (total + per_block - 1) / per_block;
        gather_seqwrite_kernel<<<blocks, threads>>>(
            m0, m1, m2, f0, f1, f2, (float4*)d_out, L);
    }
}